// round 16
// baseline (speedup 1.0000x reference)
#include <cuda_runtime.h>

// Problem constants
#define EMBED 1024
#define HEADS 16
#define HDIM  64
#define BATCH 2
#define SEQ   2048
#define MROWS (BATCH * SEQ)                       /* 4096 */
#define PLANE ((size_t)HEADS * BATCH * SEQ * HDIM) /* 4194304 */

// Scratch (device globals: allocation-free rule)
__device__ float g_QKV[3 * 4194304];               // [3][bh][s][d]
__device__ float g_O[(size_t)MROWS * EMBED];       // concat layout [m][e]

// ---------------------------------------------------------------------------
// SGEMM: C[4096,1024] = A[4096,1024] @ W[1024,1024] + bias
// 128x128 block tile, BK=8, 256 threads, 8x8 register microtile.
// mode 0: grid.z selects (q,Wq,bq)/(k,Wk,bk)/(v,Wv,bv), writes split-head
//         layout into g_QKV[z].
// mode 1: A = g_O (concat), writes row-major into Cplain (d_out).
// ---------------------------------------------------------------------------
__global__ __launch_bounds__(256) void sgemm128(
    const float* __restrict__ A0, const float* __restrict__ A1, const float* __restrict__ A2,
    const float* __restrict__ W0, const float* __restrict__ W1, const float* __restrict__ W2,
    const float* __restrict__ B0, const float* __restrict__ B1, const float* __restrict__ B2,
    float* __restrict__ Cplain, int mode)
{
    const int K = EMBED, N = EMBED;
    const int z = blockIdx.z;
    const float* A    = (mode == 1) ? g_O : (z == 0 ? A0 : (z == 1 ? A1 : A2));
    const float* W    = (z == 0 ? W0 : (z == 1 ? W1 : W2));
    const float* bias = (z == 0 ? B0 : (z == 1 ? B1 : B2));

    __shared__ float As[8][128];   // A tile transposed: As[k][m]
    __shared__ float Bs[8][128];   // W tile: Bs[k][n]

    const int tid  = threadIdx.x;
    const int brow = blockIdx.y << 7;
    const int bcol = blockIdx.x << 7;

    const int a_row = tid >> 1;          // 0..127
    const int a_col = (tid & 1) << 2;    // 0 or 4
    const int b_row = tid >> 5;          // 0..7
    const int b_col = (tid & 31) << 2;   // 0..124

    const int ty = tid >> 4;             // 0..15
    const int tx = tid & 15;             // 0..15

    float acc[8][8];
#pragma unroll
    for (int i = 0; i < 8; ++i)
#pragma unroll
        for (int j = 0; j < 8; ++j) acc[i][j] = 0.0f;

    const float* Aptr = A + (size_t)(brow + a_row) * K + a_col;
    const float* Wptr = W + (size_t)b_row * N + bcol + b_col;

    for (int k0 = 0; k0 < K; k0 += 8) {
        float4 av = *(const float4*)(Aptr + k0);
        float4 bv = *(const float4*)(Wptr + (size_t)k0 * N);
        As[a_col + 0][a_row] = av.x;
        As[a_col + 1][a_row] = av.y;
        As[a_col + 2][a_row] = av.z;
        As[a_col + 3][a_row] = av.w;
        *(float4*)&Bs[b_row][b_col] = bv;
        __syncthreads();

#pragma unroll
        for (int kk = 0; kk < 8; ++kk) {
            float ra[8], rb[8];
            float4 t0 = *(const float4*)&As[kk][ty * 8];
            float4 t1 = *(const float4*)&As[kk][ty * 8 + 4];
            ra[0] = t0.x; ra[1] = t0.y; ra[2] = t0.z; ra[3] = t0.w;
            ra[4] = t1.x; ra[5] = t1.y; ra[6] = t1.z; ra[7] = t1.w;
            float4 u0 = *(const float4*)&Bs[kk][tx * 8];
            float4 u1 = *(const float4*)&Bs[kk][tx * 8 + 4];
            rb[0] = u0.x; rb[1] = u0.y; rb[2] = u0.z; rb[3] = u0.w;
            rb[4] = u1.x; rb[5] = u1.y; rb[6] = u1.z; rb[7] = u1.w;
#pragma unroll
            for (int i = 0; i < 8; ++i)
#pragma unroll
                for (int j = 0; j < 8; ++j)
                    acc[i][j] = fmaf(ra[i], rb[j], acc[i][j]);
        }
        __syncthreads();
    }

    const int n0 = bcol + tx * 8;        // multiple of 8: never crosses a 64-col head
#pragma unroll
    for (int i = 0; i < 8; ++i) {
        const int m = brow + ty * 8 + i;
        float4 w0 = make_float4(acc[i][0] + bias[n0 + 0], acc[i][1] + bias[n0 + 1],
                                acc[i][2] + bias[n0 + 2], acc[i][3] + bias[n0 + 3]);
        float4 w1 = make_float4(acc[i][4] + bias[n0 + 4], acc[i][5] + bias[n0 + 5],
                                acc[i][6] + bias[n0 + 6], acc[i][7] + bias[n0 + 7]);
        if (mode == 1) {
            float* dst = Cplain + (size_t)m * N + n0;
            *(float4*)dst = w0;
            *(float4*)(dst + 4) = w1;
        } else {
            const int bb = m >> 11, ss = m & 2047;
            const int h = n0 >> 6, d0 = n0 & 63;
            float* dst = g_QKV + (size_t)z * PLANE +
                         (((size_t)(bb * HEADS + h) * SEQ + ss) << 6) + d0;
            *(float4*)dst = w0;
            *(float4*)(dst + 4) = w1;
        }
    }
}

// ---------------------------------------------------------------------------
// Flash attention, fp32. One block = one (bh, 64-query tile).
// 256 threads as 16x16; each thread owns a 4x4 S microtile and a 4x4 O tile.
// Row softmax statistics replicated across each 16-lane row group via
// shfl.xor butterflies (offsets 1,2,4,8 stay inside the 16-lane half-warp).
// Smem: Qt (K-transposed Q), Kt (K transposed; reused as P), Vs. 3x16KB = 48KB.
// ---------------------------------------------------------------------------
__global__ __launch_bounds__(256) void attn_kernel()
{
    __shared__ float Qt[64 * 64];    // [d][q], pre-scaled by 1/8
    __shared__ float KtPs[64 * 64];  // [d][k] during S; reused as P[q][k]
    __shared__ float Vs[64 * 64];    // [k][d]

    const int bh = blockIdx.y;
    const int q0 = blockIdx.x << 6;
    const int tid = threadIdx.x;
    const int ty = tid >> 4, tx = tid & 15;
    const int lr = tid >> 2;             // loader row 0..63
    const int lc = (tid & 3) << 2;       // loader col base 0/4/8/12

    const float* Qg = g_QKV + ((size_t)bh * SEQ + q0) * HDIM;
    const float* Kg = g_QKV + PLANE + (size_t)bh * SEQ * HDIM;
    const float* Vg = g_QKV + 2 * PLANE + (size_t)bh * SEQ * HDIM;

    // Load Q tile transposed & pre-scaled by 1/sqrt(64)
#pragma unroll
    for (int r = 0; r < 4; ++r) {
        const int d = lc + r * 16;
        float4 v = *(const float4*)&Qg[lr * 64 + d];
        Qt[(d + 0) * 64 + lr] = v.x * 0.125f;
        Qt[(d + 1) * 64 + lr] = v.y * 0.125f;
        Qt[(d + 2) * 64 + lr] = v.z * 0.125f;
        Qt[(d + 3) * 64 + lr] = v.w * 0.125f;
    }

    float m_run[4], l_run[4], o[4][4];
#pragma unroll
    for (int i = 0; i < 4; ++i) {
        m_run[i] = -3.0e38f;
        l_run[i] = 0.0f;
#pragma unroll
        for (int j = 0; j < 4; ++j) o[i][j] = 0.0f;
    }

    for (int kt = 0; kt < 32; ++kt) {
        __syncthreads();  // prev-iter PV reads done (and Qt ready on iter 0)

        const float* Kgt = Kg + (size_t)kt * 64 * 64;
        const float* Vgt = Vg + (size_t)kt * 64 * 64;
#pragma unroll
        for (int r = 0; r < 4; ++r) {
            const int d = lc + r * 16;
            float4 kv = *(const float4*)&Kgt[lr * 64 + d];
            KtPs[(d + 0) * 64 + lr] = kv.x;
            KtPs[(d + 1) * 64 + lr] = kv.y;
            KtPs[(d + 2) * 64 + lr] = kv.z;
            KtPs[(d + 3) * 64 + lr] = kv.w;
            float4 vv = *(const float4*)&Vgt[lr * 64 + d];
            *(float4*)&Vs[lr * 64 + d] = vv;
        }
        __syncthreads();

        // S = (Q/8) K^T for this 64x64 tile; 4x4 per thread
        float s[4][4];
#pragma unroll
        for (int i = 0; i < 4; ++i)
#pragma unroll
            for (int j = 0; j < 4; ++j) s[i][j] = 0.0f;

#pragma unroll
        for (int d = 0; d < 64; ++d) {
            float qa[4], kb[4];
            float4 tq = *(const float4*)&Qt[d * 64 + ty * 4];     // broadcast
            float4 tk = *(const float4*)&KtPs[d * 64 + tx * 4];   // conflict-free
            qa[0] = tq.x; qa[1] = tq.y; qa[2] = tq.z; qa[3] = tq.w;
            kb[0] = tk.x; kb[1] = tk.y; kb[2] = tk.z; kb[3] = tk.w;
#pragma unroll
            for (int i = 0; i < 4; ++i)
#pragma unroll
                for (int j = 0; j < 4; ++j)
                    s[i][j] = fmaf(qa[i], kb[j], s[i][j]);
        }
        __syncthreads();  // all Kt reads done before P overwrites the buffer

        // Online softmax update; store P into KtPs
#pragma unroll
        for (int i = 0; i < 4; ++i) {
            float rm = fmaxf(fmaxf(s[i][0], s[i][1]), fmaxf(s[i][2], s[i][3]));
            rm = fmaxf(rm, __shfl_xor_sync(0xffffffffu, rm, 1));
            rm = fmaxf(rm, __shfl_xor_sync(0xffffffffu, rm, 2));
            rm = fmaxf(rm, __shfl_xor_sync(0xffffffffu, rm, 4));
            rm = fmaxf(rm, __shfl_xor_sync(0xffffffffu, rm, 8));
            const float mn = fmaxf(m_run[i], rm);
            const float corr = __expf(m_run[i] - mn);
            m_run[i] = mn;
            const float p0 = __expf(s[i][0] - mn);
            const float p1 = __expf(s[i][1] - mn);
            const float p2 = __expf(s[i][2] - mn);
            const float p3 = __expf(s[i][3] - mn);
            float rs = (p0 + p1) + (p2 + p3);
            rs += __shfl_xor_sync(0xffffffffu, rs, 1);
            rs += __shfl_xor_sync(0xffffffffu, rs, 2);
            rs += __shfl_xor_sync(0xffffffffu, rs, 4);
            rs += __shfl_xor_sync(0xffffffffu, rs, 8);
            l_run[i] = l_run[i] * corr + rs;
            o[i][0] *= corr; o[i][1] *= corr; o[i][2] *= corr; o[i][3] *= corr;
            *(float4*)&KtPs[(ty * 4 + i) * 64 + tx * 4] = make_float4(p0, p1, p2, p3);
        }
        __syncthreads();

        // O += P @ V
#pragma unroll 8
        for (int kk = 0; kk < 64; ++kk) {
            float vv[4];
            float4 tv = *(const float4*)&Vs[kk * 64 + tx * 4];    // conflict-free
            vv[0] = tv.x; vv[1] = tv.y; vv[2] = tv.z; vv[3] = tv.w;
            float p[4];
            p[0] = KtPs[(ty * 4 + 0) * 64 + kk];                  // broadcast
            p[1] = KtPs[(ty * 4 + 1) * 64 + kk];
            p[2] = KtPs[(ty * 4 + 2) * 64 + kk];
            p[3] = KtPs[(ty * 4 + 3) * 64 + kk];
#pragma unroll
            for (int i = 0; i < 4; ++i)
#pragma unroll
                for (int j = 0; j < 4; ++j)
                    o[i][j] = fmaf(p[i], vv[j], o[i][j]);
        }
    }

    // Epilogue: normalize and write concat layout [m][h*64+d]
    const int bb = bh >> 4, h = bh & 15;
#pragma unroll
    for (int i = 0; i < 4; ++i) {
        const float inv = 1.0f / l_run[i];
        const int m = bb * SEQ + q0 + ty * 4 + i;
        float* dst = g_O + (size_t)m * EMBED + h * HDIM + tx * 4;
        *(float4*)dst = make_float4(o[i][0] * inv, o[i][1] * inv,
                                    o[i][2] * inv, o[i][3] * inv);
    }
}

// ---------------------------------------------------------------------------
// Launch: 3 fused projection GEMMs (grid.z) -> attention -> output GEMM.
// Graph-capturable: kernel launches only, no sync/alloc/memcpy.
// ---------------------------------------------------------------------------
extern "C" void kernel_launch(void* const* d_in, const int* in_sizes, int n_in,
                              void* d_out, int out_size)
{
    (void)in_sizes; (void)n_in; (void)out_size;
    const float* q  = (const float*)d_in[0];
    const float* k  = (const float*)d_in[1];
    const float* v  = (const float*)d_in[2];
    const float* Wq = (const float*)d_in[3];
    const float* bq = (const float*)d_in[4];
    const float* Wk = (const float*)d_in[5];
    const float* bk = (const float*)d_in[6];
    const float* Wv = (const float*)d_in[7];
    const float* bv = (const float*)d_in[8];
    const float* Wo = (const float*)d_in[9];
    const float* bo = (const float*)d_in[10];
    float* out = (float*)d_out;

    // Q/K/V projections, split-head output into g_QKV
    sgemm128<<<dim3(EMBED / 128, MROWS / 128, 3), 256>>>(
        q, k, v, Wq, Wk, Wv, bq, bk, bv, nullptr, 0);

    // Flash attention: 32 q-tiles x 32 (b,h) pairs
    attn_kernel<<<dim3(SEQ / 64, BATCH * HEADS), 256>>>();

    // Output projection: g_O @ Wo + bo -> d_out
    sgemm128<<<dim3(EMBED / 128, MROWS / 128, 1), 256>>>(
        nullptr, nullptr, nullptr, Wo, nullptr, nullptr, bo, nullptr, nullptr,
        out, 1);
}

// round 17
// speedup vs baseline: 1.0045x; 1.0045x over previous
#include <cuda_runtime.h>

// Problem constants
#define EMBED 1024
#define HEADS 16
#define HDIM  64
#define BATCH 2
#define SEQ   2048
#define MROWS (BATCH * SEQ)                       /* 4096 */
#define PLANE ((size_t)HEADS * BATCH * SEQ * HDIM) /* 4194304 */

// Scratch (device globals: allocation-free rule)
__device__ float g_QKV[3 * 4194304];               // [3][bh][s][d]
__device__ float g_O[(size_t)MROWS * EMBED];       // concat layout [m][e]

// ---------------------------------------------------------------------------
// SGEMM: C[4096,1024] = A[4096,1024] @ W[1024,1024] + bias
// 128x128 block tile, BK=8, 256 threads, 8x8 register microtile.
// mode 0: grid.z selects (q,Wq,bq)/(k,Wk,bk)/(v,Wv,bv), writes split-head
//         layout into g_QKV[z].
// mode 1: A = g_O (concat), writes row-major into Cplain (d_out).
// ---------------------------------------------------------------------------
__global__ __launch_bounds__(256) void sgemm128(
    const float* __restrict__ A0, const float* __restrict__ A1, const float* __restrict__ A2,
    const float* __restrict__ W0, const float* __restrict__ W1, const float* __restrict__ W2,
    const float* __restrict__ B0, const float* __restrict__ B1, const float* __restrict__ B2,
    float* __restrict__ Cplain, int mode)
{
    const int K = EMBED, N = EMBED;
    const int z = blockIdx.z;
    const float* A    = (mode == 1) ? g_O : (z == 0 ? A0 : (z == 1 ? A1 : A2));
    const float* W    = (z == 0 ? W0 : (z == 1 ? W1 : W2));
    const float* bias = (z == 0 ? B0 : (z == 1 ? B1 : B2));

    __shared__ float As[8][128];   // A tile transposed: As[k][m]
    __shared__ float Bs[8][128];   // W tile: Bs[k][n]

    const int tid  = threadIdx.x;
    const int brow = blockIdx.y << 7;
    const int bcol = blockIdx.x << 7;

    const int a_row = tid >> 1;          // 0..127
    const int a_col = (tid & 1) << 2;    // 0 or 4
    const int b_row = tid >> 5;          // 0..7
    const int b_col = (tid & 31) << 2;   // 0..124

    const int ty = tid >> 4;             // 0..15
    const int tx = tid & 15;             // 0..15

    float acc[8][8];
#pragma unroll
    for (int i = 0; i < 8; ++i)
#pragma unroll
        for (int j = 0; j < 8; ++j) acc[i][j] = 0.0f;

    const float* Aptr = A + (size_t)(brow + a_row) * K + a_col;
    const float* Wptr = W + (size_t)b_row * N + bcol + b_col;

    for (int k0 = 0; k0 < K; k0 += 8) {
        float4 av = *(const float4*)(Aptr + k0);
        float4 bv = *(const float4*)(Wptr + (size_t)k0 * N);
        As[a_col + 0][a_row] = av.x;
        As[a_col + 1][a_row] = av.y;
        As[a_col + 2][a_row] = av.z;
        As[a_col + 3][a_row] = av.w;
        *(float4*)&Bs[b_row][b_col] = bv;
        __syncthreads();

#pragma unroll
        for (int kk = 0; kk < 8; ++kk) {
            float ra[8], rb[8];
            float4 t0 = *(const float4*)&As[kk][ty * 8];
            float4 t1 = *(const float4*)&As[kk][ty * 8 + 4];
            ra[0] = t0.x; ra[1] = t0.y; ra[2] = t0.z; ra[3] = t0.w;
            ra[4] = t1.x; ra[5] = t1.y; ra[6] = t1.z; ra[7] = t1.w;
            float4 u0 = *(const float4*)&Bs[kk][tx * 8];
            float4 u1 = *(const float4*)&Bs[kk][tx * 8 + 4];
            rb[0] = u0.x; rb[1] = u0.y; rb[2] = u0.z; rb[3] = u0.w;
            rb[4] = u1.x; rb[5] = u1.y; rb[6] = u1.z; rb[7] = u1.w;
#pragma unroll
            for (int i = 0; i < 8; ++i)
#pragma unroll
                for (int j = 0; j < 8; ++j)
                    acc[i][j] = fmaf(ra[i], rb[j], acc[i][j]);
        }
        __syncthreads();
    }

    const int n0 = bcol + tx * 8;        // multiple of 8: never crosses a 64-col head
#pragma unroll
    for (int i = 0; i < 8; ++i) {
        const int m = brow + ty * 8 + i;
        float4 w0 = make_float4(acc[i][0] + bias[n0 + 0], acc[i][1] + bias[n0 + 1],
                                acc[i][2] + bias[n0 + 2], acc[i][3] + bias[n0 + 3]);
        float4 w1 = make_float4(acc[i][4] + bias[n0 + 4], acc[i][5] + bias[n0 + 5],
                                acc[i][6] + bias[n0 + 6], acc[i][7] + bias[n0 + 7]);
        if (mode == 1) {
            float* dst = Cplain + (size_t)m * N + n0;
            *(float4*)dst = w0;
            *(float4*)(dst + 4) = w1;
        } else {
            const int bb = m >> 11, ss = m & 2047;
            const int h = n0 >> 6, d0 = n0 & 63;
            float* dst = g_QKV + (size_t)z * PLANE +
                         (((size_t)(bb * HEADS + h) * SEQ + ss) << 6) + d0;
            *(float4*)dst = w0;
            *(float4*)(dst + 4) = w1;
        }
    }
}

// ---------------------------------------------------------------------------
// Flash attention, fp32. One block = one (bh, 64-query tile).
// 256 threads as 16x16; each thread owns a 4x4 S microtile and a 4x4 O tile.
// Row softmax statistics replicated across each 16-lane row group via
// shfl.xor butterflies (offsets 1,2,4,8 stay inside the 16-lane half-warp).
// Smem: Qt (K-transposed Q), Kt (K transposed; reused as P), Vs. 3x16KB = 48KB.
// ---------------------------------------------------------------------------
__global__ __launch_bounds__(256) void attn_kernel()
{
    __shared__ float Qt[64 * 64];    // [d][q], pre-scaled by 1/8
    __shared__ float KtPs[64 * 64];  // [d][k] during S; reused as P[q][k]
    __shared__ float Vs[64 * 64];    // [k][d]

    const int bh = blockIdx.y;
    const int q0 = blockIdx.x << 6;
    const int tid = threadIdx.x;
    const int ty = tid >> 4, tx = tid & 15;
    const int lr = tid >> 2;             // loader row 0..63
    const int lc = (tid & 3) << 2;       // loader col base 0/4/8/12

    const float* Qg = g_QKV + ((size_t)bh * SEQ + q0) * HDIM;
    const float* Kg = g_QKV + PLANE + (size_t)bh * SEQ * HDIM;
    const float* Vg = g_QKV + 2 * PLANE + (size_t)bh * SEQ * HDIM;

    // Load Q tile transposed & pre-scaled by 1/sqrt(64)
#pragma unroll
    for (int r = 0; r < 4; ++r) {
        const int d = lc + r * 16;
        float4 v = *(const float4*)&Qg[lr * 64 + d];
        Qt[(d + 0) * 64 + lr] = v.x * 0.125f;
        Qt[(d + 1) * 64 + lr] = v.y * 0.125f;
        Qt[(d + 2) * 64 + lr] = v.z * 0.125f;
        Qt[(d + 3) * 64 + lr] = v.w * 0.125f;
    }

    float m_run[4], l_run[4], o[4][4];
#pragma unroll
    for (int i = 0; i < 4; ++i) {
        m_run[i] = -3.0e38f;
        l_run[i] = 0.0f;
#pragma unroll
        for (int j = 0; j < 4; ++j) o[i][j] = 0.0f;
    }

    for (int kt = 0; kt < 32; ++kt) {
        __syncthreads();  // prev-iter PV reads done (and Qt ready on iter 0)

        const float* Kgt = Kg + (size_t)kt * 64 * 64;
        const float* Vgt = Vg + (size_t)kt * 64 * 64;
#pragma unroll
        for (int r = 0; r < 4; ++r) {
            const int d = lc + r * 16;
            float4 kv = *(const float4*)&Kgt[lr * 64 + d];
            KtPs[(d + 0) * 64 + lr] = kv.x;
            KtPs[(d + 1) * 64 + lr] = kv.y;
            KtPs[(d + 2) * 64 + lr] = kv.z;
            KtPs[(d + 3) * 64 + lr] = kv.w;
            float4 vv = *(const float4*)&Vgt[lr * 64 + d];
            *(float4*)&Vs[lr * 64 + d] = vv;
        }
        __syncthreads();

        // S = (Q/8) K^T for this 64x64 tile; 4x4 per thread
        float s[4][4];
#pragma unroll
        for (int i = 0; i < 4; ++i)
#pragma unroll
            for (int j = 0; j < 4; ++j) s[i][j] = 0.0f;

#pragma unroll
        for (int d = 0; d < 64; ++d) {
            float qa[4], kb[4];
            float4 tq = *(const float4*)&Qt[d * 64 + ty * 4];     // broadcast
            float4 tk = *(const float4*)&KtPs[d * 64 + tx * 4];   // conflict-free
            qa[0] = tq.x; qa[1] = tq.y; qa[2] = tq.z; qa[3] = tq.w;
            kb[0] = tk.x; kb[1] = tk.y; kb[2] = tk.z; kb[3] = tk.w;
#pragma unroll
            for (int i = 0; i < 4; ++i)
#pragma unroll
                for (int j = 0; j < 4; ++j)
                    s[i][j] = fmaf(qa[i], kb[j], s[i][j]);
        }
        __syncthreads();  // all Kt reads done before P overwrites the buffer

        // Online softmax update; store P into KtPs
#pragma unroll
        for (int i = 0; i < 4; ++i) {
            float rm = fmaxf(fmaxf(s[i][0], s[i][1]), fmaxf(s[i][2], s[i][3]));
            rm = fmaxf(rm, __shfl_xor_sync(0xffffffffu, rm, 1));
            rm = fmaxf(rm, __shfl_xor_sync(0xffffffffu, rm, 2));
            rm = fmaxf(rm, __shfl_xor_sync(0xffffffffu, rm, 4));
            rm = fmaxf(rm, __shfl_xor_sync(0xffffffffu, rm, 8));
            const float mn = fmaxf(m_run[i], rm);
            const float corr = __expf(m_run[i] - mn);
            m_run[i] = mn;
            const float p0 = __expf(s[i][0] - mn);
            const float p1 = __expf(s[i][1] - mn);
            const float p2 = __expf(s[i][2] - mn);
            const float p3 = __expf(s[i][3] - mn);
            float rs = (p0 + p1) + (p2 + p3);
            rs += __shfl_xor_sync(0xffffffffu, rs, 1);
            rs += __shfl_xor_sync(0xffffffffu, rs, 2);
            rs += __shfl_xor_sync(0xffffffffu, rs, 4);
            rs += __shfl_xor_sync(0xffffffffu, rs, 8);
            l_run[i] = l_run[i] * corr + rs;
            o[i][0] *= corr; o[i][1] *= corr; o[i][2] *= corr; o[i][3] *= corr;
            *(float4*)&KtPs[(ty * 4 + i) * 64 + tx * 4] = make_float4(p0, p1, p2, p3);
        }
        __syncthreads();

        // O += P @ V
#pragma unroll 8
        for (int kk = 0; kk < 64; ++kk) {
            float vv[4];
            float4 tv = *(const float4*)&Vs[kk * 64 + tx * 4];    // conflict-free
            vv[0] = tv.x; vv[1] = tv.y; vv[2] = tv.z; vv[3] = tv.w;
            float p[4];
            p[0] = KtPs[(ty * 4 + 0) * 64 + kk];                  // broadcast
            p[1] = KtPs[(ty * 4 + 1) * 64 + kk];
            p[2] = KtPs[(ty * 4 + 2) * 64 + kk];
            p[3] = KtPs[(ty * 4 + 3) * 64 + kk];
#pragma unroll
            for (int i = 0; i < 4; ++i)
#pragma unroll
                for (int j = 0; j < 4; ++j)
                    o[i][j] = fmaf(p[i], vv[j], o[i][j]);
        }
    }

    // Epilogue: normalize and write concat layout [m][h*64+d]
    const int bb = bh >> 4, h = bh & 15;
#pragma unroll
    for (int i = 0; i < 4; ++i) {
        const float inv = 1.0f / l_run[i];
        const int m = bb * SEQ + q0 + ty * 4 + i;
        float* dst = g_O + (size_t)m * EMBED + h * HDIM + tx * 4;
        *(float4*)dst = make_float4(o[i][0] * inv, o[i][1] * inv,
                                    o[i][2] * inv, o[i][3] * inv);
    }
}

// ---------------------------------------------------------------------------
// Launch: 3 fused projection GEMMs (grid.z) -> attention -> output GEMM.
// Graph-capturable: kernel launches only, no sync/alloc/memcpy.
// ---------------------------------------------------------------------------
extern "C" void kernel_launch(void* const* d_in, const int* in_sizes, int n_in,
                              void* d_out, int out_size)
{
    (void)in_sizes; (void)n_in; (void)out_size;
    const float* q  = (const float*)d_in[0];
    const float* k  = (const float*)d_in[1];
    const float* v  = (const float*)d_in[2];
    const float* Wq = (const float*)d_in[3];
    const float* bq = (const float*)d_in[4];
    const float* Wk = (const float*)d_in[5];
    const float* bk = (const float*)d_in[6];
    const float* Wv = (const float*)d_in[7];
    const float* bv = (const float*)d_in[8];
    const float* Wo = (const float*)d_in[9];
    const float* bo = (const float*)d_in[10];
    float* out = (float*)d_out;

    // Q/K/V projections, split-head output into g_QKV
    sgemm128<<<dim3(EMBED / 128, MROWS / 128, 3), 256>>>(
        q, k, v, Wq, Wk, Wv, bq, bk, bv, nullptr, 0);

    // Flash attention: 32 q-tiles x 32 (b,h) pairs
    attn_kernel<<<dim3(SEQ / 64, BATCH * HEADS), 256>>>();

    // Output projection: g_O @ Wo + bo -> d_out
    sgemm128<<<dim3(EMBED / 128, MROWS / 128, 1), 256>>>(
        nullptr, nullptr, nullptr, Wo, nullptr, nullptr, bo, nullptr, nullptr,
        out, 1);
}